// round 16
// baseline (speedup 1.0000x reference)
#include <cuda_runtime.h>
#include <cuda_fp16.h>
#include <math.h>
#include <stdint.h>

#define BATCH   14336
#define DIM     512
#define NCLS    7
#define MPC     2048
#define NPAIRS  13
#define BN_EPS  1e-5f

#define BM      128
#define BN      128
#define NCH     8                 // 8 K-chunks of 64 halves
#define NB_WITHIN (NCLS * 136)    // 952 triangular tiles
#define NBLOCKS   (NB_WITHIN + 6 * 256)  // 2488

// per-stage dynamic smem: [A: 4 subs x 4KB | B: 4 subs x 4KB] = 32KB; 3 stages
#define STG_BYTES 32768
#define DSMEM     (3 * STG_BYTES)   // 98304

// t = exp(-d2/20) = 2^(d2 * S2E)
#define S2E  (-0.0721347520444482f)

// -------------------- device scratch --------------------
__device__ float        g_norms [BATCH];
__device__ float        g_logits[BATCH * NCLS];
__device__ float        g_bn1   [NCLS];
__device__ float        g_bn2   [NCLS];
__device__ float        g_kderow[BATCH];
__device__ double       g_ksum  [NPAIRS];
__device__ float        g_w     [NCLS];
__device__ unsigned int g_done;
__device__ __half       g_hi[BATCH * DIM];

__constant__ int c_pairA[NPAIRS] = {0,1,2,3,4,5,6, 1,2,3,4,5,6};
__constant__ int c_pairB[NPAIRS] = {0,1,2,3,4,5,6, 0,0,0,0,0,0};

// -------------------- PTX helpers --------------------
__device__ __forceinline__ uint32_t smem_u32(const void* p) {
    uint32_t a;
    asm("{ .reg .u64 t; cvta.to.shared.u64 t, %1; cvt.u32.u64 %0, t; }" : "=r"(a) : "l"(p));
    return a;
}
__device__ __forceinline__ float ex2f(float x) {
    float y;
    asm("ex2.approx.f32 %0, %1;" : "=f"(y) : "f"(x));
    return y;
}
#define CPA16(sm, g) asm volatile("cp.async.cg.shared.global [%0], [%1], 16;" :: "r"(sm), "l"(g) : "memory")
#define CP_COMMIT()  asm volatile("cp.async.commit_group;" ::: "memory")
#define CP_WAIT1()   asm volatile("cp.async.wait_group 1;" ::: "memory")
#define CP_WAIT0()   asm volatile("cp.async.wait_group 0;" ::: "memory")

__device__ __forceinline__ void ldsm4(uint32_t* r, uint32_t addr) {
    asm volatile("ldmatrix.sync.aligned.m8n8.x4.shared.b16 {%0,%1,%2,%3}, [%4];"
                 : "=r"(r[0]), "=r"(r[1]), "=r"(r[2]), "=r"(r[3]) : "r"(addr));
}
__device__ __forceinline__ void mma16816(float* c, const uint32_t* a, const uint32_t* b) {
    asm volatile(
        "mma.sync.aligned.m16n8k16.row.col.f32.f16.f16.f32 "
        "{%0,%1,%2,%3}, {%4,%5,%6,%7}, {%8,%9}, {%0,%1,%2,%3};"
        : "+f"(c[0]), "+f"(c[1]), "+f"(c[2]), "+f"(c[3])
        : "r"(a[0]), "r"(a[1]), "r"(a[2]), "r"(a[3]), "r"(b[0]), "r"(b[1]));
}

// -------------------- kernel 0: zero accumulators --------------------
__global__ void zero_kernel() {
    int t = blockIdx.x * blockDim.x + threadIdx.x;
    if (t < NPAIRS) g_ksum[t] = 0.0;
    if (t < NCLS) { g_bn1[t] = 0.0f; g_bn2[t] = 0.0f; }
    if (t == 31) g_done = 0u;
    for (int i = t; i < BATCH; i += blockDim.x * gridDim.x) g_kderow[i] = 0.0f;
}

// -------------------- kernel 1: fused prep --------------------
// fp32 -> fp16 + fc logits + row norms + BN partial sums.
__global__ void __launch_bounds__(256) prep_kernel(
    const float* __restrict__ fea, const float* __restrict__ Wfc)
{
    __shared__ float4 Ws[NCLS * (DIM / 4)];
    __shared__ float bs1[NCLS], bs2[NCLS];
    for (int i = threadIdx.x; i < NCLS * (DIM / 4); i += blockDim.x)
        Ws[i] = ((const float4*)Wfc)[i];
    if (threadIdx.x < NCLS) { bs1[threadIdx.x] = 0.0f; bs2[threadIdx.x] = 0.0f; }
    __syncthreads();

    int warp = (blockIdx.x * blockDim.x + threadIdx.x) >> 5;
    int lane = threadIdx.x & 31;

    if (warp < BATCH) {
        const float4* row = (const float4*)(fea + (size_t)warp * DIM);
        __half2* hp = (__half2*)g_hi + (size_t)warp * (DIM / 2);

        float acc[NCLS];
        #pragma unroll
        for (int c = 0; c < NCLS; c++) acc[c] = 0.0f;
        float nrm = 0.0f;

        #pragma unroll
        for (int t = 0; t < 4; t++) {
            int idx = lane + 32 * t;
            float4 v = row[idx];
            nrm += v.x * v.x + v.y * v.y + v.z * v.z + v.w * v.w;
            #pragma unroll
            for (int c = 0; c < NCLS; c++) {
                float4 w = Ws[c * 128 + idx];
                acc[c] += v.x * w.x + v.y * w.y + v.z * w.z + v.w * w.w;
            }
            hp[idx * 2 + 0] = __halves2half2(__float2half_rn(v.x), __float2half_rn(v.y));
            hp[idx * 2 + 1] = __halves2half2(__float2half_rn(v.z), __float2half_rn(v.w));
        }
        #pragma unroll
        for (int off = 16; off; off >>= 1) {
            nrm += __shfl_down_sync(0xffffffffu, nrm, off);
            #pragma unroll
            for (int c = 0; c < NCLS; c++)
                acc[c] += __shfl_down_sync(0xffffffffu, acc[c], off);
        }
        if (lane == 0) {
            g_norms[warp] = nrm;
            #pragma unroll
            for (int c = 0; c < NCLS; c++) {
                g_logits[warp * NCLS + c] = acc[c];
                atomicAdd(&bs1[c], acc[c]);
                atomicAdd(&bs2[c], acc[c] * acc[c]);
            }
        }
    }
    __syncthreads();
    if (threadIdx.x < NCLS) {
        atomicAdd(&g_bn1[threadIdx.x], bs1[threadIdx.x]);
        atomicAdd(&g_bn2[threadIdx.x], bs2[threadIdx.x]);
    }
}

// -------------------- kernel 2: BN normalize -> out --------------------
__global__ void bnorm_kernel(const float* __restrict__ gamma,
                             const float* __restrict__ beta, float* __restrict__ out) {
    int i = blockIdx.x * blockDim.x + threadIdx.x;
    if (i < BATCH * NCLS) {
        int c = i % NCLS;
        float mu  = g_bn1[c] * (1.0f / BATCH);
        float var = g_bn2[c] * (1.0f / BATCH) - mu * mu;
        float rstd = gamma[c] * rsqrtf(var + BN_EPS);
        out[i] = (g_logits[i] - mu) * rstd + beta[c];
    }
}

// -------------------- kernel 3: fp16 mma gram, BK=64 chunks, 3-stage ring ----
__global__ void __launch_bounds__(256, 2) mmd_mma_kernel() {
    extern __shared__ char dsm[];
    __shared__ float s_na[128], s_nb[128];
    __shared__ float s_red[256];
    __shared__ float s_krow[128], s_kcol[128];

    uint32_t tilesb = smem_u32(dsm);
    int tid  = threadIdx.x;
    int wid  = tid >> 5;
    int lane = tid & 31;
    int warpM = wid >> 2, warpN = wid & 3;

    // ---- blockIdx -> (pair, tr, tc) ----
    int pair, tr, tc;
    {
        int b = blockIdx.x;
        if (b < NB_WITHIN) {
            pair = b / 136;
            int t = b - pair * 136;
            tr = 0;
            int rowlen = 16;
            while (t >= rowlen) { t -= rowlen; rowlen--; tr++; }
            tc = tr + t;
        } else {
            int b2 = b - NB_WITHIN;
            pair = NCLS + (b2 >> 8);
            int tile = b2 & 255;
            tr = tile >> 4; tc = tile & 15;
        }
    }
    bool within = (pair < NCLS);
    int row0 = c_pairA[pair] * MPC + tr * BM;
    int col0 = c_pairB[pair] * MPC + tc * BN;

    // ---- norms + kde accumulators ----
    if (tid < 128) {
        s_na[tid] = g_norms[row0 + tid];
        s_krow[tid] = 0.0f;
    } else {
        s_nb[tid - 128] = g_norms[col0 + tid - 128];
        s_kcol[tid - 128] = 0.0f;
    }

    // ---- producer addressing: per chunk, 4 subs x 16B for A and B each ----
    int pr = tid >> 1;                 // row 0..127
    int pc = tid & 1;                  // 16B half within a 32B sub-row
    uint32_t psoff = (uint32_t)(pr * 32 + ((pc ^ ((pr >> 2) & 1)) << 4));
    const char* gAh = (const char*)g_hi + (size_t)(row0 + pr) * (DIM * 2) + pc * 16;
    const char* gBh = (const char*)g_hi + (size_t)(col0 + pr) * (DIM * 2) + pc * 16;
    uint32_t sAh = tilesb + psoff;       // sub s at +s*4096; B at +16384; stage at +stg*STG_BYTES
    uint32_t sBh = sAh + 16384;

    // ---- ldmatrix lane addressing ----
    int g = lane >> 3;
    int arow = warpM * 64 + (lane & 7) + ((g & 1) << 3);
    uint32_t aoff = (uint32_t)(arow * 32 + (((g >> 1) ^ ((arow >> 2) & 1)) << 4));
    int brow = warpN * 32 + (lane & 7) + ((g >> 1) << 3);
    uint32_t boff = (uint32_t)(brow * 32 + (((g & 1) ^ ((brow >> 2) & 1)) << 4));

    float c[4][4][4];
    #pragma unroll
    for (int i = 0; i < 4; i++)
        #pragma unroll
        for (int j = 0; j < 4; j++)
            #pragma unroll
            for (int k = 0; k < 4; k++) c[i][j][k] = 0.0f;

    // ---- prologue: stages 0,1 (chunks 0,1; 128B of K per chunk) ----
    #pragma unroll
    for (int st = 0; st < 2; st++) {
        uint32_t so = (uint32_t)(st * STG_BYTES);
        int go = st * 128;
        #pragma unroll
        for (int s = 0; s < 4; s++) {
            CPA16(sAh + so + s * 4096, gAh + go + s * 32);
            CPA16(sBh + so + s * 4096, gBh + go + s * 32);
        }
        CP_COMMIT();
    }

    // ---- mainloop: ONE barrier per 64-K chunk ----
    for (int ch = 0; ch < NCH; ch++) {
        if (ch == NCH - 1) { CP_WAIT0(); } else { CP_WAIT1(); }
        __syncthreads();

        if (ch + 2 < NCH) {
            uint32_t so = (uint32_t)(((ch + 2) % 3) * STG_BYTES);
            int go = (ch + 2) * 128;
            #pragma unroll
            for (int s = 0; s < 4; s++) {
                CPA16(sAh + so + s * 4096, gAh + go + s * 32);
                CPA16(sBh + so + s * 4096, gBh + go + s * 32);
            }
            CP_COMMIT();
        }

        uint32_t base = tilesb + (uint32_t)((ch % 3) * STG_BYTES);
        #pragma unroll
        for (int sub = 0; sub < 4; sub++) {
            uint32_t sa = base + (uint32_t)(sub * 4096);
            uint32_t sb = sa + 16384;
            uint32_t a[4][4], bh[2][4];
            #pragma unroll
            for (int mt = 0; mt < 4; mt++) ldsm4(a[mt], sa + aoff + mt * 512);
            #pragma unroll
            for (int np = 0; np < 2; np++) ldsm4(bh[np], sb + boff + np * 512);
            #pragma unroll
            for (int mt = 0; mt < 4; mt++)
                #pragma unroll
                for (int nt = 0; nt < 4; nt++)
                    mma16816(c[mt][nt], a[mt], &bh[nt >> 1][(nt & 1) * 2]);
        }
    }
    __syncthreads();

    // ---- epilogue: d2 -> 5-bandwidth kernel sum + KDE ----
    int rbase = warpM * 64 + (lane >> 2);
    int cbase = warpN * 32 + (lane & 3) * 2;

    float naS[8], nbS[8];
    #pragma unroll
    for (int mt = 0; mt < 4; mt++)
        #pragma unroll
        for (int h = 0; h < 2; h++)
            naS[mt * 2 + h] = s_na[rbase + mt * 16 + h * 8] * S2E;
    #pragma unroll
    for (int nt = 0; nt < 4; nt++)
        #pragma unroll
        for (int e = 0; e < 2; e++)
            nbS[nt * 2 + e] = s_nb[cbase + nt * 8 + e] * S2E;

    const float m2S = -2.0f * S2E;
    float ks[4] = {0.0f, 0.0f, 0.0f, 0.0f};
    float kdr[8], kdc[8];
    #pragma unroll
    for (int i = 0; i < 8; i++) { kdr[i] = 0.0f; kdc[i] = 0.0f; }

    #pragma unroll
    for (int mt = 0; mt < 4; mt++) {
        #pragma unroll
        for (int nt = 0; nt < 4; nt++) {
            #pragma unroll
            for (int r = 0; r < 4; r++) {
                int h = r >> 1, e = r & 1;
                float arg = fminf(fmaf(c[mt][nt][r], m2S, naS[mt * 2 + h] + nbS[nt * 2 + e]), 0.0f);
                float t = ex2f(arg);
                float t2 = t * t, t4 = t2 * t2, t8 = t4 * t4;
                ks[r] += (t + t2) + (t4 + t8) + t8 * t8;
                if (within) {
                    float kd = ex2f(arg * 250.0f);   // exp(-12.5 d2)
                    kdr[mt * 2 + h] += kd;
                    kdc[nt * 2 + e] += kd;
                }
            }
        }
    }
    float ksum = (ks[0] + ks[1]) + (ks[2] + ks[3]);

    if (within) {
        #pragma unroll
        for (int i = 0; i < 8; i++) {
            float v = kdr[i];
            v += __shfl_xor_sync(0xffffffffu, v, 1);
            v += __shfl_xor_sync(0xffffffffu, v, 2);
            if ((lane & 3) == 0)
                atomicAdd(&s_krow[warpM * 64 + (i >> 1) * 16 + (i & 1) * 8 + (lane >> 2)], v);
        }
        if (tr != tc) {
            #pragma unroll
            for (int j = 0; j < 8; j++) {
                float v = kdc[j];
                v += __shfl_xor_sync(0xffffffffu, v, 4);
                v += __shfl_xor_sync(0xffffffffu, v, 8);
                v += __shfl_xor_sync(0xffffffffu, v, 16);
                if (lane < 4)
                    atomicAdd(&s_kcol[warpN * 32 + (j >> 1) * 8 + (j & 1) + lane * 2], v);
            }
        }
    }

    s_red[tid] = ksum;
    __syncthreads();
    for (int s = 128; s; s >>= 1) {
        if (tid < s) s_red[tid] += s_red[tid + s];
        __syncthreads();
    }
    if (tid == 0) {
        double wt = (within && tr != tc) ? 2.0 : 1.0;
        atomicAdd(&g_ksum[pair], (double)s_red[0] * wt);
    }
    if (within && tid < 128) {
        atomicAdd(&g_kderow[row0 + tid], s_krow[tid]);
        if (tr != tc) atomicAdd(&g_kderow[col0 + tid], s_kcol[tid]);
    }
}

// -------------------- kernel 4: finalize (7 class blocks + last-block loss) ----
__global__ void finalize_kernel(float* __restrict__ out, int out_size) {
    const float LOG_NORM = -0.5f * (float)DIM * __logf(2.0f * (float)M_PI * 0.04f)
                           - __logf((float)MPC);
    __shared__ float red[256];

    int c   = blockIdx.x;            // 0..6
    int tid = threadIdx.x;

    float v = 0.0f;
    #pragma unroll
    for (int i = 0; i < MPC / 256; i++) {
        float logp = __logf(g_kderow[c * MPC + tid + i * 256]) + LOG_NORM;
        v += __fdividef(1.0f, logp);
    }
    red[tid] = v;
    __syncthreads();
    for (int s = 128; s; s >>= 1) {
        if (tid < s) red[tid] += red[tid + s];
        __syncthreads();
    }

    if (tid == 0) {
        g_w[c] = 1.0f / (red[0] + 1e-5f);
        __threadfence();
        unsigned int old = atomicAdd(&g_done, 1u);
        if (old == NCLS - 1) {
            g_done = 0u;     // reset for next graph replay
            const double inv = 1.0 / ((double)MPC * (double)MPC);
            double S[NCLS];
            for (int k = 0; k < NCLS; k++) S[k] = g_ksum[k] * inv;
            double X[NCLS];
            for (int i = 1; i < NCLS; i++) X[i] = g_ksum[NCLS + i - 1] * inv;
            double loss = (S[0] + S[1] - 2.0 * X[1]) * (double)g_w[0];
            for (int i = 1; i < NCLS; i++)
                loss += (S[i] + S[0] - 2.0 * X[i]) * (double)g_w[i];
            out[out_size - 1] = (float)(-loss);
        }
    }
}

// -------------------- launch --------------------
// mmd_mma_kernel is launch #4 (ncu's profiled slot).
extern "C" void kernel_launch(void* const* d_in, const int* in_sizes, int n_in,
                              void* d_out, int out_size) {
    const float* fea   = (const float*)d_in[0];
    const float* Wfc   = (const float*)d_in[1];
    const float* gamma = (const float*)d_in[2];
    const float* beta  = (const float*)d_in[3];
    float* out = (float*)d_out;

    static bool attr_set = false;
    if (!attr_set) {
        cudaFuncSetAttribute(mmd_mma_kernel, cudaFuncAttributeMaxDynamicSharedMemorySize, DSMEM);
        attr_set = true;
    }

    zero_kernel<<<56, 256>>>();
    prep_kernel<<<BATCH / 8, 256>>>(fea, Wfc);
    bnorm_kernel<<<(BATCH * NCLS + 255) / 256, 256>>>(gamma, beta, out);
    mmd_mma_kernel<<<NBLOCKS, 256, DSMEM>>>();
    finalize_kernel<<<NCLS, 256>>>(out, out_size);
}

// round 17
// speedup vs baseline: 1.1167x; 1.1167x over previous
#include <cuda_runtime.h>
#include <cuda_fp16.h>
#include <math.h>
#include <stdint.h>

#define BATCH   14336
#define DIM     512
#define NCLS    7
#define MPC     2048
#define NPAIRS  13
#define BN_EPS  1e-5f

#define BM      128
#define BN      128
#define NSTG    16                // 16 K-stages of 32
#define NB_WITHIN (NCLS * 136)    // 952 triangular tiles
#define NBLOCKS   (NB_WITHIN + 6 * 256)  // 2488

// per-stage dynamic smem: [Ahi0|Ahi1|Bhi0|Bhi1] x 4KB = 16KB; 3 stages
#define STG_BYTES 16384
#define DSMEM     (3 * STG_BYTES)   // 49152

// t = exp(-d2/20) = 2^(d2 * S2E)
#define S2E  (-0.0721347520444482f)

// -------------------- device scratch --------------------
__device__ float        g_norms [BATCH];
__device__ float        g_logits[BATCH * NCLS];
__device__ float        g_bn1   [NCLS];
__device__ float        g_bn2   [NCLS];
__device__ float        g_kderow[BATCH];
__device__ double       g_ksum  [NPAIRS];
__device__ float        g_w     [NCLS];
__device__ unsigned int g_done;
__device__ __half       g_hi[BATCH * DIM];

__constant__ int c_pairA[NPAIRS] = {0,1,2,3,4,5,6, 1,2,3,4,5,6};
__constant__ int c_pairB[NPAIRS] = {0,1,2,3,4,5,6, 0,0,0,0,0,0};

// -------------------- PTX helpers --------------------
__device__ __forceinline__ uint32_t smem_u32(const void* p) {
    uint32_t a;
    asm("{ .reg .u64 t; cvta.to.shared.u64 t, %1; cvt.u32.u64 %0, t; }" : "=r"(a) : "l"(p));
    return a;
}
__device__ __forceinline__ float ex2f(float x) {
    float y;
    asm("ex2.approx.f32 %0, %1;" : "=f"(y) : "f"(x));
    return y;
}
#define CPA16(sm, g) asm volatile("cp.async.cg.shared.global [%0], [%1], 16;" :: "r"(sm), "l"(g) : "memory")
#define CP_COMMIT()  asm volatile("cp.async.commit_group;" ::: "memory")
#define CP_WAIT1()   asm volatile("cp.async.wait_group 1;" ::: "memory")
#define CP_WAIT0()   asm volatile("cp.async.wait_group 0;" ::: "memory")

__device__ __forceinline__ void ldsm4(uint32_t* r, uint32_t addr) {
    asm volatile("ldmatrix.sync.aligned.m8n8.x4.shared.b16 {%0,%1,%2,%3}, [%4];"
                 : "=r"(r[0]), "=r"(r[1]), "=r"(r[2]), "=r"(r[3]) : "r"(addr));
}
__device__ __forceinline__ void mma16816(float* c, const uint32_t* a, const uint32_t* b) {
    asm volatile(
        "mma.sync.aligned.m16n8k16.row.col.f32.f16.f16.f32 "
        "{%0,%1,%2,%3}, {%4,%5,%6,%7}, {%8,%9}, {%0,%1,%2,%3};"
        : "+f"(c[0]), "+f"(c[1]), "+f"(c[2]), "+f"(c[3])
        : "r"(a[0]), "r"(a[1]), "r"(a[2]), "r"(a[3]), "r"(b[0]), "r"(b[1]));
}

// -------------------- kernel 0: zero accumulators --------------------
__global__ void zero_kernel() {
    int t = blockIdx.x * blockDim.x + threadIdx.x;
    if (t < NPAIRS) g_ksum[t] = 0.0;
    if (t < NCLS) { g_bn1[t] = 0.0f; g_bn2[t] = 0.0f; }
    if (t == 31) g_done = 0u;
    for (int i = t; i < BATCH; i += blockDim.x * gridDim.x) g_kderow[i] = 0.0f;
}

// -------------------- kernel 1: fused prep --------------------
// fp32 -> fp16 + fc logits + row norms + BN partial sums.
__global__ void __launch_bounds__(256) prep_kernel(
    const float* __restrict__ fea, const float* __restrict__ Wfc)
{
    __shared__ float4 Ws[NCLS * (DIM / 4)];
    __shared__ float bs1[NCLS], bs2[NCLS];
    for (int i = threadIdx.x; i < NCLS * (DIM / 4); i += blockDim.x)
        Ws[i] = ((const float4*)Wfc)[i];
    if (threadIdx.x < NCLS) { bs1[threadIdx.x] = 0.0f; bs2[threadIdx.x] = 0.0f; }
    __syncthreads();

    int warp = (blockIdx.x * blockDim.x + threadIdx.x) >> 5;
    int lane = threadIdx.x & 31;

    if (warp < BATCH) {
        const float4* row = (const float4*)(fea + (size_t)warp * DIM);
        __half2* hp = (__half2*)g_hi + (size_t)warp * (DIM / 2);

        float acc[NCLS];
        #pragma unroll
        for (int c = 0; c < NCLS; c++) acc[c] = 0.0f;
        float nrm = 0.0f;

        #pragma unroll
        for (int t = 0; t < 4; t++) {
            int idx = lane + 32 * t;
            float4 v = row[idx];
            nrm += v.x * v.x + v.y * v.y + v.z * v.z + v.w * v.w;
            #pragma unroll
            for (int c = 0; c < NCLS; c++) {
                float4 w = Ws[c * 128 + idx];
                acc[c] += v.x * w.x + v.y * w.y + v.z * w.z + v.w * w.w;
            }
            hp[idx * 2 + 0] = __halves2half2(__float2half_rn(v.x), __float2half_rn(v.y));
            hp[idx * 2 + 1] = __halves2half2(__float2half_rn(v.z), __float2half_rn(v.w));
        }
        #pragma unroll
        for (int off = 16; off; off >>= 1) {
            nrm += __shfl_down_sync(0xffffffffu, nrm, off);
            #pragma unroll
            for (int c = 0; c < NCLS; c++)
                acc[c] += __shfl_down_sync(0xffffffffu, acc[c], off);
        }
        if (lane == 0) {
            g_norms[warp] = nrm;
            #pragma unroll
            for (int c = 0; c < NCLS; c++) {
                g_logits[warp * NCLS + c] = acc[c];
                atomicAdd(&bs1[c], acc[c]);
                atomicAdd(&bs2[c], acc[c] * acc[c]);
            }
        }
    }
    __syncthreads();
    if (threadIdx.x < NCLS) {
        atomicAdd(&g_bn1[threadIdx.x], bs1[threadIdx.x]);
        atomicAdd(&g_bn2[threadIdx.x], bs2[threadIdx.x]);
    }
}

// -------------------- kernel 2: BN normalize -> out --------------------
__global__ void bnorm_kernel(const float* __restrict__ gamma,
                             const float* __restrict__ beta, float* __restrict__ out) {
    int i = blockIdx.x * blockDim.x + threadIdx.x;
    if (i < BATCH * NCLS) {
        int c = i % NCLS;
        float mu  = g_bn1[c] * (1.0f / BATCH);
        float var = g_bn2[c] * (1.0f / BATCH) - mu * mu;
        float rstd = gamma[c] * rsqrtf(var + BN_EPS);
        out[i] = (g_logits[i] - mu) * rstd + beta[c];
    }
}

// -------------------- kernel 3: fp16 mma gram, BK=32, one barrier/chunk ----
__global__ void __launch_bounds__(256, 2) mmd_mma_kernel() {
    extern __shared__ char dsm[];
    __shared__ float s_na[128], s_nb[128];
    __shared__ float s_red[256];
    __shared__ float s_krow[128], s_kcol[128];

    uint32_t tilesb = smem_u32(dsm);
    int tid  = threadIdx.x;
    int wid  = tid >> 5;
    int lane = tid & 31;
    int warpM = wid >> 2, warpN = wid & 3;

    // ---- blockIdx -> (pair, tr, tc) ----
    int pair, tr, tc;
    {
        int b = blockIdx.x;
        if (b < NB_WITHIN) {
            pair = b / 136;
            int t = b - pair * 136;
            tr = 0;
            int rowlen = 16;
            while (t >= rowlen) { t -= rowlen; rowlen--; tr++; }
            tc = tr + t;
        } else {
            int b2 = b - NB_WITHIN;
            pair = NCLS + (b2 >> 8);
            int tile = b2 & 255;
            tr = tile >> 4; tc = tile & 15;
        }
    }
    bool within = (pair < NCLS);
    int row0 = c_pairA[pair] * MPC + tr * BM;
    int col0 = c_pairB[pair] * MPC + tc * BN;

    // ---- norms + kde accumulators ----
    if (tid < 128) {
        s_na[tid] = g_norms[row0 + tid];
        s_krow[tid] = 0.0f;
    } else {
        s_nb[tid - 128] = g_norms[col0 + tid - 128];
        s_kcol[tid - 128] = 0.0f;
    }

    // ---- producer addressing ----
    int pr = tid >> 1;                 // row 0..127
    int pc = tid & 1;                  // 16B half within a 32B (16-k) row
    uint32_t psoff = (uint32_t)(pr * 32 + ((pc ^ ((pr >> 2) & 1)) << 4));
    const char* gAh = (const char*)g_hi + (size_t)(row0 + pr) * (DIM * 2) + pc * 16;
    const char* gBh = (const char*)g_hi + (size_t)(col0 + pr) * (DIM * 2) + pc * 16;
    uint32_t sAh = tilesb + psoff;       // sub s at +s*4096; stage at +stg*STG_BYTES
    uint32_t sBh = sAh + 8192;

    // ---- ldmatrix lane addressing ----
    int g = lane >> 3;
    int arow = warpM * 64 + (lane & 7) + ((g & 1) << 3);
    uint32_t aoff = (uint32_t)(arow * 32 + (((g >> 1) ^ ((arow >> 2) & 1)) << 4));
    int brow = warpN * 32 + (lane & 7) + ((g >> 1) << 3);
    uint32_t boff = (uint32_t)(brow * 32 + (((g & 1) ^ ((brow >> 2) & 1)) << 4));

    float c[4][4][4];
    #pragma unroll
    for (int i = 0; i < 4; i++)
        #pragma unroll
        for (int j = 0; j < 4; j++)
            #pragma unroll
            for (int k = 0; k < 4; k++) c[i][j][k] = 0.0f;

    // ---- prologue: stages 0,1 ----
    #pragma unroll
    for (int st = 0; st < 2; st++) {
        #pragma unroll
        for (int s = 0; s < 2; s++) {
            uint32_t so = (uint32_t)(st * STG_BYTES + s * 4096);
            int go = st * 64 + s * 32;
            CPA16(sAh + so, gAh + go);
            CPA16(sBh + so, gBh + go);
        }
        CP_COMMIT();
    }

    // ---- mainloop: ONE barrier per chunk ----
    for (int ch = 0; ch < NSTG; ch++) {
        if (ch == NSTG - 1) { CP_WAIT0(); } else { CP_WAIT1(); }
        __syncthreads();

        if (ch + 2 < NSTG) {
            uint32_t so = (uint32_t)(((ch + 2) % 3) * STG_BYTES);
            int go = (ch + 2) * 64;
            #pragma unroll
            for (int s = 0; s < 2; s++) {
                CPA16(sAh + so + s * 4096, gAh + go + s * 32);
                CPA16(sBh + so + s * 4096, gBh + go + s * 32);
            }
            CP_COMMIT();
        }

        uint32_t base = tilesb + (uint32_t)((ch % 3) * STG_BYTES);
        #pragma unroll
        for (int sub = 0; sub < 2; sub++) {
            uint32_t sb = base + (uint32_t)(sub * 4096);
            uint32_t a[4][4], bh[2][4];
            #pragma unroll
            for (int mt = 0; mt < 4; mt++) ldsm4(a[mt], sb + aoff + mt * 512);
            #pragma unroll
            for (int np = 0; np < 2; np++) ldsm4(bh[np], sb + 8192 + boff + np * 512);
            #pragma unroll
            for (int mt = 0; mt < 4; mt++)
                #pragma unroll
                for (int nt = 0; nt < 4; nt++)
                    mma16816(c[mt][nt], a[mt], &bh[nt >> 1][(nt & 1) * 2]);
        }
    }
    __syncthreads();

    // ---- epilogue: d2 -> 5-bandwidth kernel sum + KDE ----
    int rbase = warpM * 64 + (lane >> 2);
    int cbase = warpN * 32 + (lane & 3) * 2;

    float naS[8], nbS[8];
    #pragma unroll
    for (int mt = 0; mt < 4; mt++)
        #pragma unroll
        for (int h = 0; h < 2; h++)
            naS[mt * 2 + h] = s_na[rbase + mt * 16 + h * 8] * S2E;
    #pragma unroll
    for (int nt = 0; nt < 4; nt++)
        #pragma unroll
        for (int e = 0; e < 2; e++)
            nbS[nt * 2 + e] = s_nb[cbase + nt * 8 + e] * S2E;

    const float m2S = -2.0f * S2E;
    float ks[4] = {0.0f, 0.0f, 0.0f, 0.0f};
    float kdr[8], kdc[8];
    #pragma unroll
    for (int i = 0; i < 8; i++) { kdr[i] = 0.0f; kdc[i] = 0.0f; }

    #pragma unroll
    for (int mt = 0; mt < 4; mt++) {
        #pragma unroll
        for (int nt = 0; nt < 4; nt++) {
            #pragma unroll
            for (int r = 0; r < 4; r++) {
                int h = r >> 1, e = r & 1;
                float arg = fminf(fmaf(c[mt][nt][r], m2S, naS[mt * 2 + h] + nbS[nt * 2 + e]), 0.0f);
                float t = ex2f(arg);
                float t2 = t * t, t4 = t2 * t2, t8 = t4 * t4;
                ks[r] += (t + t2) + (t4 + t8) + t8 * t8;
                if (within) {
                    float kd = ex2f(arg * 250.0f);   // exp(-12.5 d2)
                    kdr[mt * 2 + h] += kd;
                    kdc[nt * 2 + e] += kd;
                }
            }
        }
    }
    float ksum = (ks[0] + ks[1]) + (ks[2] + ks[3]);

    if (within) {
        #pragma unroll
        for (int i = 0; i < 8; i++) {
            float v = kdr[i];
            v += __shfl_xor_sync(0xffffffffu, v, 1);
            v += __shfl_xor_sync(0xffffffffu, v, 2);
            if ((lane & 3) == 0)
                atomicAdd(&s_krow[warpM * 64 + (i >> 1) * 16 + (i & 1) * 8 + (lane >> 2)], v);
        }
        if (tr != tc) {
            #pragma unroll
            for (int j = 0; j < 8; j++) {
                float v = kdc[j];
                v += __shfl_xor_sync(0xffffffffu, v, 4);
                v += __shfl_xor_sync(0xffffffffu, v, 8);
                v += __shfl_xor_sync(0xffffffffu, v, 16);
                if (lane < 4)
                    atomicAdd(&s_kcol[warpN * 32 + (j >> 1) * 8 + (j & 1) + lane * 2], v);
            }
        }
    }

    s_red[tid] = ksum;
    __syncthreads();
    for (int s = 128; s; s >>= 1) {
        if (tid < s) s_red[tid] += s_red[tid + s];
        __syncthreads();
    }
    if (tid == 0) {
        double wt = (within && tr != tc) ? 2.0 : 1.0;
        atomicAdd(&g_ksum[pair], (double)s_red[0] * wt);
    }
    if (within && tid < 128) {
        atomicAdd(&g_kderow[row0 + tid], s_krow[tid]);
        if (tr != tc) atomicAdd(&g_kderow[col0 + tid], s_kcol[tid]);
    }
}

// -------------------- kernel 4: finalize (7 class blocks + last-block loss) ----
__global__ void finalize_kernel(float* __restrict__ out, int out_size) {
    const float LOG_NORM = -0.5f * (float)DIM * __logf(2.0f * (float)M_PI * 0.04f)
                           - __logf((float)MPC);
    __shared__ float red[256];

    int c   = blockIdx.x;            // 0..6
    int tid = threadIdx.x;

    float v = 0.0f;
    #pragma unroll
    for (int i = 0; i < MPC / 256; i++) {
        float logp = __logf(g_kderow[c * MPC + tid + i * 256]) + LOG_NORM;
        v += __fdividef(1.0f, logp);
    }
    red[tid] = v;
    __syncthreads();
    for (int s = 128; s; s >>= 1) {
        if (tid < s) red[tid] += red[tid + s];
        __syncthreads();
    }

    if (tid == 0) {
        g_w[c] = 1.0f / (red[0] + 1e-5f);
        __threadfence();
        unsigned int old = atomicAdd(&g_done, 1u);
        if (old == NCLS - 1) {
            g_done = 0u;     // reset for next graph replay
            const double inv = 1.0 / ((double)MPC * (double)MPC);
            double S[NCLS];
            for (int k = 0; k < NCLS; k++) S[k] = g_ksum[k] * inv;
            double X[NCLS];
            for (int i = 1; i < NCLS; i++) X[i] = g_ksum[NCLS + i - 1] * inv;
            double loss = (S[0] + S[1] - 2.0 * X[1]) * (double)g_w[0];
            for (int i = 1; i < NCLS; i++)
                loss += (S[i] + S[0] - 2.0 * X[i]) * (double)g_w[i];
            out[out_size - 1] = (float)(-loss);
        }
    }
}

// -------------------- launch --------------------
// mmd_mma_kernel is launch #4 (ncu's profiled slot).
extern "C" void kernel_launch(void* const* d_in, const int* in_sizes, int n_in,
                              void* d_out, int out_size) {
    const float* fea   = (const float*)d_in[0];
    const float* Wfc   = (const float*)d_in[1];
    const float* gamma = (const float*)d_in[2];
    const float* beta  = (const float*)d_in[3];
    float* out = (float*)d_out;

    static bool attr_set = false;
    if (!attr_set) {
        cudaFuncSetAttribute(mmd_mma_kernel, cudaFuncAttributeMaxDynamicSharedMemorySize, DSMEM);
        attr_set = true;
    }

    zero_kernel<<<56, 256>>>();
    prep_kernel<<<BATCH / 8, 256>>>(fea, Wfc);
    bnorm_kernel<<<(BATCH * NCLS + 255) / 256, 256>>>(gamma, beta, out);
    mmd_mma_kernel<<<NBLOCKS, 256, DSMEM>>>();
    finalize_kernel<<<NCLS, 256>>>(out, out_size);
}